// round 2
// baseline (speedup 1.0000x reference)
#include <cuda_runtime.h>
#include <math.h>

// ---------------- problem constants ----------------
#define DN     160
#define MS     64
#define MV     32
#define NGROUP 16
#define FCIN   128
#define MAXN   10000
#define EPB    16
#define PITCH  20

#define INV8        0.125f
#define INV16       0.0625f
#define INV_SQRT32  0.17677669529663687f
#define INV_SQRT128 0.08838834764831845f
#define INV_SQRT3   0.5773502691896258f
#define INV_FAN     0.05892556509887896f   /* 1/sqrt(3*MS+3*MV) */
#define LN_EPS      1e-5f

// ---------------- device scratch (no allocs allowed) ----------------
__device__ float g_s  [MAXN * MS];
__device__ float g_v  [MAXN * MV * 3];
__device__ float g_scs[MAXN * MS];
__device__ float g_scv[MAXN * MV * 3];
__device__ float g_ns [MAXN * MS];
__device__ float g_nv [MAXN * MV * 3];
__device__ float g_ps [MAXN * MS];
__device__ float g_pv [MAXN * MV * 3];
__device__ float g_stats[NGROUP * 4];
__device__ float g_norm [NGROUP * 3];

__device__ __forceinline__ float silu_f(float x) { return x / (1.f + __expf(-x)); }
__device__ __forceinline__ float sigm_f(float x) { return 1.f / (1.f + __expf(-x)); }

// packed f32x2 helpers (Blackwell FFMA2)
#define FMA2(acc, x, w) asm("fma.rn.f32x2 %0, %1, %2, %0;" : "+l"(acc) : "l"(x), "l"(w))
__device__ __forceinline__ unsigned long long bcast2(float w) {
    unsigned long long r;
    asm("mov.b64 %0, {%1, %1};" : "=l"(r) : "f"(w));
    return r;
}
__device__ __forceinline__ float2 unpk(unsigned long long v) {
    float2 r;
    asm("mov.b64 {%0, %1}, %2;" : "=f"(r.x), "=f"(r.y) : "l"(v));
    return r;
}

// ---------------- zero scratch ----------------
__global__ void k_zero(int N) {
    int tot = N * DN + NGROUP * 4;
    for (int i = blockIdx.x * blockDim.x + threadIdx.x; i < tot; i += gridDim.x * blockDim.x) {
        if (i < N * MS)      g_ns[i] = 0.f;
        else if (i < N * DN) g_nv[i - N * MS] = 0.f;
        else                 g_stats[i - N * DN] = 0.f;
    }
}

// ---------------- node pre: lp + self-connection ----------------
__global__ __launch_bounds__(96) void k_node_pre(
    const float* __restrict__ nf, const float* __restrict__ onehot,
    const float* __restrict__ lpWs, const float* __restrict__ lpbs,
    const float* __restrict__ lpWv,
    const float* __restrict__ scWs, const float* __restrict__ scWv)
{
    const int n = blockIdx.x;
    const int t = threadIdx.x;
    __shared__ float ss[MS];
    __shared__ float sv[MV * 3];
    __shared__ int ssp;

    if (t < MS) ss[t] = nf[n * DN + t];
    sv[t] = nf[n * DN + MS + t];
    if (t == 0) {
        int sp = 0; float best = onehot[n * 4];
        #pragma unroll
        for (int k = 1; k < 4; k++) { float v = onehot[n * 4 + k]; if (v > best) { best = v; sp = k; } }
        ssp = sp;
    }
    __syncthreads();
    const int sp = ssp;

    if (t < MS) {
        float a = 0.f, b = 0.f;
        #pragma unroll 8
        for (int u = 0; u < MS; u++) {
            float x = ss[u];
            a += x * lpWs[u * MS + t];
            b += x * scWs[(u * 4 + sp) * MS + t];
        }
        g_s  [n * MS + t] = a * INV8 + lpbs[t];
        g_scs[n * MS + t] = b * INV16;
    }
    {
        const int w = t / 3, i = t - w * 3;
        float a = 0.f, b = 0.f;
        #pragma unroll 8
        for (int u = 0; u < MV; u++) {
            float x = sv[u * 3 + i];
            a += x * lpWv[u * MV + w];
            b += x * scWv[(u * 4 + sp) * MV + w];
        }
        g_v  [n * 96 + w * 3 + i] = a * INV_SQRT32;
        g_scv[n * 96 + w * 3 + i] = b * INV_SQRT128;
    }
}

// ---------------- edge kernel: 16 edges / 128-thread block, f32x2 math ----------------
struct EdgeSmem {
    float S1 [192][PITCH];
    float V1 [3][96][PITCH];
    float DD [96][PITCH];
    float ELE[128][PITCH];
    float H1 [64][PITCH];
    float H2 [64][PITCH];
    float WFC[96][PITCH];
    float T1 [32][PITCH];
    float SG [32][PITCH];
    float SH [EPB][4];
    int   I[EPB];
    int   J[EPB];
    int   OK[EPB];
};

__global__ __launch_bounds__(128) void k_edge(
    const float* __restrict__ edge_sh, const float* __restrict__ edge_fea,
    const float* __restrict__ ele,     const int*   __restrict__ edge_index,
    const float* __restrict__ Wss0, const float* __restrict__ Wvv0,
    const float* __restrict__ Wssg, const float* __restrict__ Wvvg,
    const float* __restrict__ Wsv1, const float* __restrict__ Wvs1,
    const float* __restrict__ fW1, const float* __restrict__ fb1,
    const float* __restrict__ fW2, const float* __restrict__ fb2,
    const float* __restrict__ fW3, const float* __restrict__ fb3,
    int E)
{
    extern __shared__ char raw[];
    EdgeSmem& sm = *reinterpret_cast<EdgeSmem*>(raw);
    const int t  = threadIdx.x;
    const int e0 = blockIdx.x * EPB;

    if (t < EPB) {
        int eg = e0 + t;
        int ok = (eg < E);
        sm.OK[t] = ok;
        sm.I[t]  = ok ? edge_index[eg]     : 0;
        sm.J[t]  = ok ? edge_index[E + eg] : 0;
    }
    if (t >= 64 && t < 64 + EPB * 4) {
        int q = t - 64;
        int e = q >> 2, k = q & 3;
        int eg = e0 + e;
        sm.SH[e][k] = (eg < E) ? edge_sh[eg * 4 + k] : 0.f;
    }
    __syncthreads();

    // ---- stage S1 = [s_i | s_j | es] feature-major ----
    for (int id = t; id < EPB * 192; id += 128) {
        int e = id / 192, u = id - e * 192;
        float v = 0.f;
        if (sm.OK[e]) {
            if (u < 64)       v = g_s[sm.I[e] * 64 + u];
            else if (u < 128) v = g_s[sm.J[e] * 64 + (u - 64)];
            else              v = edge_fea[(e0 + e) * DN + (u - 128)];
        }
        sm.S1[u][e] = v;
    }
    // ---- stage V1 = [v_i | v_j | ev] per xyz component, feature-major ----
    for (int id = t; id < EPB * 288; id += 128) {
        int e = id / 288, c = id - e * 288;
        float v = 0.f;
        int u, ii;
        if (c < 96) {
            if (sm.OK[e]) v = g_v[sm.I[e] * 96 + c];
            u = c / 3; ii = c - 3 * u;
        } else if (c < 192) {
            int cc = c - 96;
            if (sm.OK[e]) v = g_v[sm.J[e] * 96 + cc];
            u = 32 + cc / 3; ii = cc % 3;
        } else {
            int cc = c - 192;
            if (sm.OK[e]) v = edge_fea[(e0 + e) * DN + 64 + cc];
            u = 64 + cc / 3; ii = cc % 3;
        }
        sm.V1[ii][u][e] = v;
    }
    // ---- stage edge_length_embedded ----
    for (int id = t; id < EPB * FCIN; id += 128) {
        int e = id >> 7, u = id & 127;
        sm.ELE[u][e] = sm.OK[e] ? ele[(e0 + e) * FCIN + u] : 0.f;
    }
    __syncthreads();

    // ---- dd = <v1, sh1>/sqrt(3), feature-major ----
    for (int id = t; id < 96 * EPB; id += 128) {
        int u = id / EPB, e = id - u * EPB;
        sm.DD[u][e] = (sm.V1[0][u][e] * sm.SH[e][1] +
                       sm.V1[1][u][e] * sm.SH[e][2] +
                       sm.V1[2][u][e] * sm.SH[e][3]) * INV_SQRT3;
    }

    // ---- fc1: thread (w, grp): 64 outputs x 2 groups of 8 edges ----
    {
        const int w = t & 63, g = t >> 6;
        unsigned long long acc[4] = {0ull, 0ull, 0ull, 0ull};
        #pragma unroll 4
        for (int u = 0; u < FCIN; u++) {
            unsigned long long w2 = bcast2(__ldg(&fW1[u * 64 + w]));
            const ulonglong2* xr = reinterpret_cast<const ulonglong2*>(&sm.ELE[u][8 * g]);
            ulonglong2 x0 = xr[0], x1 = xr[1];
            FMA2(acc[0], x0.x, w2); FMA2(acc[1], x0.y, w2);
            FMA2(acc[2], x1.x, w2); FMA2(acc[3], x1.y, w2);
        }
        const float b = __ldg(&fb1[w]);
        #pragma unroll
        for (int p = 0; p < 4; p++) {
            float2 a = unpk(acc[p]);
            sm.H1[w][8 * g + 2 * p]     = silu_f(a.x + b);
            sm.H1[w][8 * g + 2 * p + 1] = silu_f(a.y + b);
        }
    }
    __syncthreads();

    // ---- fc2 ----
    {
        const int w = t & 63, g = t >> 6;
        unsigned long long acc[4] = {0ull, 0ull, 0ull, 0ull};
        #pragma unroll 4
        for (int u = 0; u < 64; u++) {
            unsigned long long w2 = bcast2(__ldg(&fW2[u * 64 + w]));
            const ulonglong2* xr = reinterpret_cast<const ulonglong2*>(&sm.H1[u][8 * g]);
            ulonglong2 x0 = xr[0], x1 = xr[1];
            FMA2(acc[0], x0.x, w2); FMA2(acc[1], x0.y, w2);
            FMA2(acc[2], x1.x, w2); FMA2(acc[3], x1.y, w2);
        }
        const float b = __ldg(&fb2[w]);
        #pragma unroll
        for (int p = 0; p < 4; p++) {
            float2 a = unpk(acc[p]);
            sm.H2[w][8 * g + 2 * p]     = silu_f(a.x + b);
            sm.H2[w][8 * g + 2 * p + 1] = silu_f(a.y + b);
        }
    }
    __syncthreads();

    // ---- fc3: 96 outputs, 8 pairs per thread ----
    if (t < 96) {
        const int w = t;
        unsigned long long acc[8] = {};
        #pragma unroll 4
        for (int u = 0; u < 64; u++) {
            unsigned long long w2 = bcast2(__ldg(&fW3[u * 96 + w]));
            const ulonglong2* xr = reinterpret_cast<const ulonglong2*>(&sm.H2[u][0]);
            ulonglong2 x0 = xr[0], x1 = xr[1], x2 = xr[2], x3 = xr[3];
            FMA2(acc[0], x0.x, w2); FMA2(acc[1], x0.y, w2);
            FMA2(acc[2], x1.x, w2); FMA2(acc[3], x1.y, w2);
            FMA2(acc[4], x2.x, w2); FMA2(acc[5], x2.y, w2);
            FMA2(acc[6], x3.x, w2); FMA2(acc[7], x3.y, w2);
        }
        const float b = __ldg(&fb3[w]);
        #pragma unroll
        for (int p = 0; p < 8; p++) {
            float2 a = unpk(acc[p]);
            sm.WFC[w][2 * p]     = a.x + b;
            sm.WFC[w][2 * p + 1] = a.y + b;
        }
    }
    __syncthreads();

    // ---- phase D: zs (warps 0-1) | zg (warp 2) | t1 (warp 3) ----
    if (t < 64) {
        const int w = t;
        unsigned long long aA[8] = {}, aB[8] = {};
        #pragma unroll 2
        for (int u = 0; u < 192; u++) {
            unsigned long long w2 = bcast2(__ldg(&Wss0[u * 64 + w]));
            const ulonglong2* xr = reinterpret_cast<const ulonglong2*>(&sm.S1[u][0]);
            ulonglong2 x0 = xr[0], x1 = xr[1], x2 = xr[2], x3 = xr[3];
            FMA2(aA[0], x0.x, w2); FMA2(aA[1], x0.y, w2);
            FMA2(aA[2], x1.x, w2); FMA2(aA[3], x1.y, w2);
            FMA2(aA[4], x2.x, w2); FMA2(aA[5], x2.y, w2);
            FMA2(aA[6], x3.x, w2); FMA2(aA[7], x3.y, w2);
        }
        #pragma unroll 2
        for (int u = 0; u < 96; u++) {
            unsigned long long w2 = bcast2(__ldg(&Wvv0[u * 64 + w]));
            const ulonglong2* xr = reinterpret_cast<const ulonglong2*>(&sm.DD[u][0]);
            ulonglong2 x0 = xr[0], x1 = xr[1], x2 = xr[2], x3 = xr[3];
            FMA2(aB[0], x0.x, w2); FMA2(aB[1], x0.y, w2);
            FMA2(aB[2], x1.x, w2); FMA2(aB[3], x1.y, w2);
            FMA2(aB[4], x2.x, w2); FMA2(aB[5], x2.y, w2);
            FMA2(aB[6], x3.x, w2); FMA2(aB[7], x3.y, w2);
        }
        #pragma unroll
        for (int p = 0; p < 8; p++) {
            float2 a = unpk(aA[p]), b = unpk(aB[p]);
            int e = 2 * p;
            if (sm.OK[e]) {
                float z = (a.x * sm.SH[e][0] + b.x) * INV_FAN;
                atomicAdd(&g_ns[sm.I[e] * MS + w], silu_f(z) * sm.WFC[w][e]);
            }
            e = 2 * p + 1;
            if (sm.OK[e]) {
                float z = (a.y * sm.SH[e][0] + b.y) * INV_FAN;
                atomicAdd(&g_ns[sm.I[e] * MS + w], silu_f(z) * sm.WFC[w][e]);
            }
        }
    } else if (t < 96) {
        const int w = t - 64;
        unsigned long long aA[8] = {}, aB[8] = {};
        #pragma unroll 2
        for (int u = 0; u < 192; u++) {
            unsigned long long w2 = bcast2(__ldg(&Wssg[u * 32 + w]));
            const ulonglong2* xr = reinterpret_cast<const ulonglong2*>(&sm.S1[u][0]);
            ulonglong2 x0 = xr[0], x1 = xr[1], x2 = xr[2], x3 = xr[3];
            FMA2(aA[0], x0.x, w2); FMA2(aA[1], x0.y, w2);
            FMA2(aA[2], x1.x, w2); FMA2(aA[3], x1.y, w2);
            FMA2(aA[4], x2.x, w2); FMA2(aA[5], x2.y, w2);
            FMA2(aA[6], x3.x, w2); FMA2(aA[7], x3.y, w2);
        }
        #pragma unroll 2
        for (int u = 0; u < 96; u++) {
            unsigned long long w2 = bcast2(__ldg(&Wvvg[u * 32 + w]));
            const ulonglong2* xr = reinterpret_cast<const ulonglong2*>(&sm.DD[u][0]);
            ulonglong2 x0 = xr[0], x1 = xr[1], x2 = xr[2], x3 = xr[3];
            FMA2(aB[0], x0.x, w2); FMA2(aB[1], x0.y, w2);
            FMA2(aB[2], x1.x, w2); FMA2(aB[3], x1.y, w2);
            FMA2(aB[4], x2.x, w2); FMA2(aB[5], x2.y, w2);
            FMA2(aB[6], x3.x, w2); FMA2(aB[7], x3.y, w2);
        }
        #pragma unroll
        for (int p = 0; p < 8; p++) {
            float2 a = unpk(aA[p]), b = unpk(aB[p]);
            int e = 2 * p;
            sm.SG[w][e]     = sigm_f((a.x * sm.SH[e][0] + b.x) * INV_FAN);
            sm.SG[w][e + 1] = sigm_f((a.y * sm.SH[e + 1][0] + b.y) * INV_FAN);
        }
    } else {
        const int w = t - 96;
        unsigned long long acc[8] = {};
        #pragma unroll 2
        for (int u = 0; u < 192; u++) {
            unsigned long long w2 = bcast2(__ldg(&Wsv1[u * 32 + w]));
            const ulonglong2* xr = reinterpret_cast<const ulonglong2*>(&sm.S1[u][0]);
            ulonglong2 x0 = xr[0], x1 = xr[1], x2 = xr[2], x3 = xr[3];
            FMA2(acc[0], x0.x, w2); FMA2(acc[1], x0.y, w2);
            FMA2(acc[2], x1.x, w2); FMA2(acc[3], x1.y, w2);
            FMA2(acc[4], x2.x, w2); FMA2(acc[5], x2.y, w2);
            FMA2(acc[6], x3.x, w2); FMA2(acc[7], x3.y, w2);
        }
        #pragma unroll
        for (int p = 0; p < 8; p++) {
            float2 a = unpk(acc[p]);
            sm.T1[w][2 * p]     = a.x;
            sm.T1[w][2 * p + 1] = a.y;
        }
    }
    __syncthreads();

    // ---- phase E: zv = (t1*sh1 + (v1@Wvs1)*sh0) * gate * w, scatter ----
    if (t < 96) {
        const int w = t & 31, ii = t >> 5;
        unsigned long long acc[8] = {};
        #pragma unroll 2
        for (int u = 0; u < 96; u++) {
            unsigned long long w2 = bcast2(__ldg(&Wvs1[u * 32 + w]));
            const ulonglong2* xr = reinterpret_cast<const ulonglong2*>(&sm.V1[ii][u][0]);
            ulonglong2 x0 = xr[0], x1 = xr[1], x2 = xr[2], x3 = xr[3];
            FMA2(acc[0], x0.x, w2); FMA2(acc[1], x0.y, w2);
            FMA2(acc[2], x1.x, w2); FMA2(acc[3], x1.y, w2);
            FMA2(acc[4], x2.x, w2); FMA2(acc[5], x2.y, w2);
            FMA2(acc[6], x3.x, w2); FMA2(acc[7], x3.y, w2);
        }
        #pragma unroll
        for (int p = 0; p < 8; p++) {
            float2 a = unpk(acc[p]);
            int e = 2 * p;
            if (sm.OK[e]) {
                float zv = (sm.T1[w][e] * sm.SH[e][1 + ii] + a.x * sm.SH[e][0]) * INV_FAN
                           * sm.SG[w][e] * sm.WFC[64 + w][e];
                atomicAdd(&g_nv[sm.I[e] * 96 + w * 3 + ii], zv);
            }
            e = 2 * p + 1;
            if (sm.OK[e]) {
                float zv = (sm.T1[w][e] * sm.SH[e][1 + ii] + a.y * sm.SH[e][0]) * INV_FAN
                           * sm.SG[w][e] * sm.WFC[64 + w][e];
                atomicAdd(&g_nv[sm.I[e] * 96 + w * 3 + ii], zv);
            }
        }
    }
}

// ---------------- node post ----------------
__global__ __launch_bounds__(96) void k_node_post(
    const float* __restrict__ ppWs, const float* __restrict__ ppbs,
    const float* __restrict__ ppWv, const int* __restrict__ batch)
{
    const int n = blockIdx.x;
    const int t = threadIdx.x;
    __shared__ float sns[MS];
    __shared__ float snv[MV * 3];
    __shared__ float red[3];

    if (t < MS) sns[t] = g_ns[n * MS + t];
    snv[t] = g_nv[n * 96 + t];
    if (t < 3) red[t] = 0.f;
    __syncthreads();

    float ps = 0.f, ps2 = 0.f, pv2 = 0.f;
    if (t < MS) {
        float a = 0.f;
        #pragma unroll 8
        for (int u = 0; u < MS; u++) a += sns[u] * ppWs[u * MS + t];
        float val = a * INV8 + ppbs[t] + g_scs[n * MS + t];
        g_ps[n * MS + t] = val;
        ps = val; ps2 = val * val;
    }
    {
        const int w = t / 3, i = t - w * 3;
        float a = 0.f;
        #pragma unroll 8
        for (int u = 0; u < MV; u++) a += snv[u * 3 + i] * ppWv[u * MV + w];
        float val = a * INV_SQRT32 + g_scv[n * 96 + t];
        g_pv[n * 96 + t] = val;
        pv2 = val * val;
    }
    atomicAdd(&red[0], ps);
    atomicAdd(&red[1], ps2);
    atomicAdd(&red[2], pv2);
    __syncthreads();
    if (t == 0) {
        const int g = batch[n];
        atomicAdd(&g_stats[g * 4 + 0], red[0] * (1.f / 64.f));
        atomicAdd(&g_stats[g * 4 + 1], red[1] * (1.f / 64.f));
        atomicAdd(&g_stats[g * 4 + 2], red[2] * (1.f / 96.f));
        atomicAdd(&g_stats[g * 4 + 3], 1.f);
    }
}

// ---------------- group stats finalize ----------------
__global__ void k_stats() {
    const int g = threadIdx.x;
    if (g < NGROUP) {
        float cnt = fmaxf(g_stats[g * 4 + 3], 1.f);
        float mu  = g_stats[g * 4 + 0] / cnt;
        float vs  = fmaxf(g_stats[g * 4 + 1] / cnt - mu * mu, 0.f);
        float vv  = g_stats[g * 4 + 2] / cnt;
        g_norm[g * 3 + 0] = mu;
        g_norm[g * 3 + 1] = rsqrtf(vs + LN_EPS);
        g_norm[g * 3 + 2] = rsqrtf(vv + LN_EPS);
    }
}

// ---------------- finalize output ----------------
__global__ void k_finalize(
    const float* __restrict__ nf, const int* __restrict__ batch,
    const float* __restrict__ lnws, const float* __restrict__ lnbs,
    const float* __restrict__ lnwv, float* __restrict__ out, int N)
{
    const int total = N * DN;
    for (int idx = blockIdx.x * blockDim.x + threadIdx.x; idx < total;
         idx += gridDim.x * blockDim.x) {
        const int n = idx / DN;
        const int c = idx - n * DN;
        const int g = batch[n];
        float o;
        if (c < MS) {
            float mu = g_norm[g * 3 + 0], is = g_norm[g * 3 + 1];
            o = nf[idx] + (g_ps[n * MS + c] - mu) * is * lnws[c] + lnbs[c];
        } else {
            const int u3 = c - MS;
            float iv = g_norm[g * 3 + 2];
            o = nf[idx] + g_pv[n * 96 + u3] * iv * lnwv[u3 / 3];
        }
        out[idx] = o;
    }
}

// ---------------- launch ----------------
extern "C" void kernel_launch(void* const* d_in, const int* in_sizes, int n_in,
                              void* d_out, int out_size)
{
    const float* node_fea = (const float*)d_in[0];
    const float* onehot   = (const float*)d_in[1];
    const float* edge_sh  = (const float*)d_in[2];
    const float* edge_fea = (const float*)d_in[3];
    const float* ele      = (const float*)d_in[4];
    const int*   edge_idx = (const int*)  d_in[5];
    const int*   batch    = (const int*)  d_in[6];
    const float* lpWs = (const float*)d_in[7];
    const float* lpbs = (const float*)d_in[8];
    const float* lpWv = (const float*)d_in[9];
    const float* ppWs = (const float*)d_in[10];
    const float* ppbs = (const float*)d_in[11];
    const float* ppWv = (const float*)d_in[12];
    const float* scWs = (const float*)d_in[13];
    const float* scWv = (const float*)d_in[14];
    const float* Wss0 = (const float*)d_in[15];
    const float* Wvv0 = (const float*)d_in[16];
    const float* Wssg = (const float*)d_in[17];
    const float* Wvvg = (const float*)d_in[18];
    const float* Wsv1 = (const float*)d_in[19];
    const float* Wvs1 = (const float*)d_in[20];
    const float* fW1  = (const float*)d_in[21];
    const float* fb1  = (const float*)d_in[22];
    const float* fW2  = (const float*)d_in[23];
    const float* fb2  = (const float*)d_in[24];
    const float* fW3  = (const float*)d_in[25];
    const float* fb3  = (const float*)d_in[26];
    const float* lnws = (const float*)d_in[27];
    const float* lnbs = (const float*)d_in[28];
    const float* lnwv = (const float*)d_in[29];
    float* out = (float*)d_out;

    const int N = in_sizes[0] / DN;
    const int E = in_sizes[2] / 4;

    const int smem_bytes = (int)sizeof(EdgeSmem);
    cudaFuncSetAttribute(k_edge, cudaFuncAttributeMaxDynamicSharedMemorySize, smem_bytes);

    const int zt = N * DN + NGROUP * 4;
    k_zero<<<(zt + 255) / 256, 256>>>(N);
    k_node_pre<<<N, 96>>>(node_fea, onehot, lpWs, lpbs, lpWv, scWs, scWv);
    k_edge<<<(E + EPB - 1) / EPB, 128, smem_bytes>>>(edge_sh, edge_fea, ele, edge_idx,
                                                     Wss0, Wvv0, Wssg, Wvvg, Wsv1, Wvs1,
                                                     fW1, fb1, fW2, fb2, fW3, fb3, E);
    k_node_post<<<N, 96>>>(ppWs, ppbs, ppWv, batch);
    k_stats<<<1, 32>>>();
    k_finalize<<<(N * DN + 255) / 256, 256>>>(node_fea, batch, lnws, lnbs, lnwv, out, N);
}

// round 3
// speedup vs baseline: 4.3835x; 4.3835x over previous
#include <cuda_runtime.h>
#include <math.h>

// ---------------- problem constants ----------------
#define DN     160
#define MS     64
#define MV     32
#define NGROUP 16
#define FCIN   128
#define MAXN   10000
#define EPB    8

#define INV8        0.125f
#define INV16       0.0625f
#define INV_SQRT32  0.17677669529663687f
#define INV_SQRT128 0.08838834764831845f
#define INV_SQRT3   0.5773502691896258f
#define INV_FAN     0.05892556509887896f   /* 1/sqrt(3*MS+3*MV) */
#define LN_EPS      1e-5f

// ---------------- device scratch ----------------
__device__ float g_scs[MAXN * MS];
__device__ float g_scv[MAXN * MV * 3];
__device__ float g_ns [MAXN * MS];
__device__ float g_nv [MAXN * MV * 3];
__device__ float g_ps [MAXN * MS];
__device__ float g_pv [MAXN * MV * 3];
__device__ float g_stats[NGROUP * 4];
__device__ float g_norm [NGROUP * 3];

// per-node precomputed partial products, packed {P_c0, P_c1, P_c2, A}
__device__ float4 g_zsI[MAXN * 64];   // Wvv0 rows 0:32 (/sqrt3), Wss0 rows 0:64
__device__ float4 g_zsJ[MAXN * 64];   // Wvv0 rows 32:64,          Wss0 rows 64:128
__device__ float4 g_zgI[MAXN * 32];   // Wvvg rows 0:32,           Wssg rows 0:64
__device__ float4 g_zgJ[MAXN * 32];   // Wvvg rows 32:64,          Wssg rows 64:128
__device__ float4 g_svI[MAXN * 32];   // Wvs1 rows 0:32 (no sqrt3),Wsv1 rows 0:64
__device__ float4 g_svJ[MAXN * 32];   // Wvs1 rows 32:64,          Wsv1 rows 64:128

__device__ __forceinline__ float silu_f(float x) { return x / (1.f + __expf(-x)); }
__device__ __forceinline__ float sigm_f(float x) { return 1.f / (1.f + __expf(-x)); }

// ---------------- zero scratch ----------------
__global__ void k_zero(int N) {
    int tot = N * DN + NGROUP * 4;
    for (int i = blockIdx.x * blockDim.x + threadIdx.x; i < tot; i += gridDim.x * blockDim.x) {
        if (i < N * MS)      g_ns[i] = 0.f;
        else if (i < N * DN) g_nv[i - N * MS] = 0.f;
        else                 g_stats[i - N * DN] = 0.f;
    }
}

// ---------------- node pre: lp + self-connection + edge-partial precompute ----------------
__global__ __launch_bounds__(128) void k_node_pre(
    const float* __restrict__ nf, const float* __restrict__ onehot,
    const float* __restrict__ lpWs, const float* __restrict__ lpbs,
    const float* __restrict__ lpWv,
    const float* __restrict__ scWs, const float* __restrict__ scWv,
    const float* __restrict__ Wss0, const float* __restrict__ Wvv0,
    const float* __restrict__ Wssg, const float* __restrict__ Wvvg,
    const float* __restrict__ Wsv1, const float* __restrict__ Wvs1)
{
    const int n = blockIdx.x;
    const int t = threadIdx.x;
    __shared__ float sIn [MS];
    __shared__ float vIn [MV * 3];
    __shared__ float sO  [MS];
    __shared__ float vO  [MV * 3];
    __shared__ int ssp;

    if (t < MS) sIn[t] = nf[n * DN + t];
    if (t < 96) vIn[t] = nf[n * DN + MS + t];
    if (t == 0) {
        int sp = 0; float best = onehot[n * 4];
        #pragma unroll
        for (int k = 1; k < 4; k++) { float v = onehot[n * 4 + k]; if (v > best) { best = v; sp = k; } }
        ssp = sp;
    }
    __syncthreads();
    const int sp = ssp;

    if (t < MS) {
        float a = 0.f, b = 0.f;
        #pragma unroll 8
        for (int u = 0; u < MS; u++) {
            float x = sIn[u];
            a += x * lpWs[u * MS + t];
            b += x * scWs[(u * 4 + sp) * MS + t];
        }
        sO[t] = a * INV8 + lpbs[t];
        g_scs[n * MS + t] = b * INV16;
    }
    if (t < 96) {
        const int w = t / 3, i = t - w * 3;
        float a = 0.f, b = 0.f;
        #pragma unroll 8
        for (int u = 0; u < MV; u++) {
            float x = vIn[u * 3 + i];
            a += x * lpWv[u * MV + w];
            b += x * scWv[(u * 4 + sp) * MV + w];
        }
        vO[w * 3 + i] = a * INV_SQRT32;
        g_scv[n * 96 + w * 3 + i] = b * INV_SQRT128;
    }
    __syncthreads();

    // ---- precompute per-node partials ----
    if (t < 64) {
        const int w = t;
        float p0 = 0.f, p1 = 0.f, p2 = 0.f, q0 = 0.f, q1 = 0.f, q2 = 0.f;
        #pragma unroll 4
        for (int u = 0; u < 32; u++) {
            float wa = Wvv0[u * 64 + w];
            float wb = Wvv0[(32 + u) * 64 + w];
            float x0 = vO[u * 3], x1 = vO[u * 3 + 1], x2 = vO[u * 3 + 2];
            p0 += x0 * wa; p1 += x1 * wa; p2 += x2 * wa;
            q0 += x0 * wb; q1 += x1 * wb; q2 += x2 * wb;
        }
        float a = 0.f, b = 0.f;
        #pragma unroll 8
        for (int u = 0; u < 64; u++) {
            float x = sO[u];
            a += x * Wss0[u * 64 + w];
            b += x * Wss0[(64 + u) * 64 + w];
        }
        g_zsI[n * 64 + w] = make_float4(p0 * INV_SQRT3, p1 * INV_SQRT3, p2 * INV_SQRT3, a);
        g_zsJ[n * 64 + w] = make_float4(q0 * INV_SQRT3, q1 * INV_SQRT3, q2 * INV_SQRT3, b);
    } else if (t < 96) {
        const int w = t - 64;
        float p0 = 0.f, p1 = 0.f, p2 = 0.f, q0 = 0.f, q1 = 0.f, q2 = 0.f;
        #pragma unroll 4
        for (int u = 0; u < 32; u++) {
            float wa = Wvvg[u * 32 + w];
            float wb = Wvvg[(32 + u) * 32 + w];
            float x0 = vO[u * 3], x1 = vO[u * 3 + 1], x2 = vO[u * 3 + 2];
            p0 += x0 * wa; p1 += x1 * wa; p2 += x2 * wa;
            q0 += x0 * wb; q1 += x1 * wb; q2 += x2 * wb;
        }
        float a = 0.f, b = 0.f;
        #pragma unroll 8
        for (int u = 0; u < 64; u++) {
            float x = sO[u];
            a += x * Wssg[u * 32 + w];
            b += x * Wssg[(64 + u) * 32 + w];
        }
        g_zgI[n * 32 + w] = make_float4(p0 * INV_SQRT3, p1 * INV_SQRT3, p2 * INV_SQRT3, a);
        g_zgJ[n * 32 + w] = make_float4(q0 * INV_SQRT3, q1 * INV_SQRT3, q2 * INV_SQRT3, b);
    } else {
        const int w = t - 96;
        float p0 = 0.f, p1 = 0.f, p2 = 0.f, q0 = 0.f, q1 = 0.f, q2 = 0.f;
        #pragma unroll 4
        for (int u = 0; u < 32; u++) {
            float wa = Wvs1[u * 32 + w];
            float wb = Wvs1[(32 + u) * 32 + w];
            float x0 = vO[u * 3], x1 = vO[u * 3 + 1], x2 = vO[u * 3 + 2];
            p0 += x0 * wa; p1 += x1 * wa; p2 += x2 * wa;
            q0 += x0 * wb; q1 += x1 * wb; q2 += x2 * wb;
        }
        float a = 0.f, b = 0.f;
        #pragma unroll 8
        for (int u = 0; u < 64; u++) {
            float x = sO[u];
            a += x * Wsv1[u * 32 + w];
            b += x * Wsv1[(64 + u) * 32 + w];
        }
        g_svI[n * 32 + w] = make_float4(p0, p1, p2, a);   // no sqrt3 on Wvs1 path
        g_svJ[n * 32 + w] = make_float4(q0, q1, q2, b);
    }
}

// ---------------- edge kernel: 8 edges / 128-thread block ----------------
__global__ __launch_bounds__(128) void k_edge(
    const float* __restrict__ edge_sh, const float* __restrict__ edge_fea,
    const float* __restrict__ ele,     const int*   __restrict__ edge_index,
    const float* __restrict__ Wss0, const float* __restrict__ Wvv0,
    const float* __restrict__ Wssg, const float* __restrict__ Wvvg,
    const float* __restrict__ Wsv1, const float* __restrict__ Wvs1,
    const float* __restrict__ fW1, const float* __restrict__ fb1,
    const float* __restrict__ fW2, const float* __restrict__ fb2,
    const float* __restrict__ fW3, const float* __restrict__ fb3,
    int E)
{
    __shared__ __align__(16) float sES [EPB][64];      // edge scalar features
    __shared__ __align__(16) float sEV [EPB][3][32];   // edge vector features, comp-major
    __shared__ __align__(16) float sDD [EPB][32];      // (ev . sh1)/sqrt3
    __shared__ __align__(16) float sELE[EPB][FCIN];
    __shared__ __align__(16) float sH1 [EPB][64];
    __shared__ __align__(16) float sH2 [EPB][64];
    __shared__ __align__(16) float sWFC[EPB][96];
    __shared__ float sSG[EPB][32];
    __shared__ float sT1[EPB][32];                     // es-part of t1
    __shared__ float sSH[EPB][4];
    __shared__ int   sI[EPB], sJ[EPB], sOK[EPB];

    const int t  = threadIdx.x;
    const int e0 = blockIdx.x * EPB;

    if (t < EPB) {
        int eg = e0 + t;
        int ok = (eg < E);
        sOK[t] = ok;
        sI[t]  = ok ? edge_index[eg]     : 0;
        sJ[t]  = ok ? edge_index[E + eg] : 0;
    }
    if (t >= 32 && t < 32 + EPB * 4) {
        int q = t - 32;
        int e = q >> 2, k = q & 3;
        int eg = e0 + e;
        sSH[e][k] = (eg < E) ? edge_sh[eg * 4 + k] : 0.f;
    }
    __syncthreads();

    // ---- stage edge features ----
    for (int id = t; id < EPB * 64; id += 128) {
        int e = id >> 6, u = id & 63;
        sES[e][u] = sOK[e] ? edge_fea[(e0 + e) * DN + u] : 0.f;
    }
    for (int id = t; id < EPB * 96; id += 128) {
        int e = id / 96, c = id - e * 96;
        int u = c / 3, ii = c - u * 3;
        sEV[e][ii][u] = sOK[e] ? edge_fea[(e0 + e) * DN + 64 + c] : 0.f;
    }
    for (int id = t; id < EPB * FCIN; id += 128) {
        int e = id >> 7, u = id & 127;
        sELE[e][u] = sOK[e] ? ele[(e0 + e) * FCIN + u] : 0.f;
    }
    __syncthreads();

    // ---- ddev = (ev . sh1)/sqrt3 ----
    for (int id = t; id < EPB * 32; id += 128) {
        int e = id >> 5, u = id & 31;
        sDD[e][u] = (sEV[e][0][u] * sSH[e][1] + sEV[e][1][u] * sSH[e][2] +
                     sEV[e][2][u] * sSH[e][3]) * INV_SQRT3;
    }

    // ---- fc1 ----
    {
        const int w = t & 63, half = t >> 6;
        float acc[4] = {0.f, 0.f, 0.f, 0.f};
        #pragma unroll 4
        for (int u4 = 0; u4 < FCIN / 4; u4++) {
            const float w0 = fW1[(u4 * 4 + 0) * 64 + w];
            const float w1 = fW1[(u4 * 4 + 1) * 64 + w];
            const float w2 = fW1[(u4 * 4 + 2) * 64 + w];
            const float w3 = fW1[(u4 * 4 + 3) * 64 + w];
            #pragma unroll
            for (int k = 0; k < 4; k++) {
                float4 x = reinterpret_cast<const float4*>(sELE[half + 2 * k])[u4];
                acc[k] += x.x * w0 + x.y * w1 + x.z * w2 + x.w * w3;
            }
        }
        const float b = fb1[w];
        #pragma unroll
        for (int k = 0; k < 4; k++) sH1[half + 2 * k][w] = silu_f(acc[k] + b);
    }
    __syncthreads();

    // ---- fc2 ----
    {
        const int w = t & 63, half = t >> 6;
        float acc[4] = {0.f, 0.f, 0.f, 0.f};
        #pragma unroll 4
        for (int u4 = 0; u4 < 16; u4++) {
            const float w0 = fW2[(u4 * 4 + 0) * 64 + w];
            const float w1 = fW2[(u4 * 4 + 1) * 64 + w];
            const float w2 = fW2[(u4 * 4 + 2) * 64 + w];
            const float w3 = fW2[(u4 * 4 + 3) * 64 + w];
            #pragma unroll
            for (int k = 0; k < 4; k++) {
                float4 x = reinterpret_cast<const float4*>(sH1[half + 2 * k])[u4];
                acc[k] += x.x * w0 + x.y * w1 + x.z * w2 + x.w * w3;
            }
        }
        const float b = fb2[w];
        #pragma unroll
        for (int k = 0; k < 4; k++) sH2[half + 2 * k][w] = silu_f(acc[k] + b);
    }
    __syncthreads();

    // ---- fc3 ----
    if (t < 96) {
        const int w = t;
        float acc[EPB];
        #pragma unroll
        for (int e = 0; e < EPB; e++) acc[e] = 0.f;
        #pragma unroll 4
        for (int u4 = 0; u4 < 16; u4++) {
            const float w0 = fW3[(u4 * 4 + 0) * 96 + w];
            const float w1 = fW3[(u4 * 4 + 1) * 96 + w];
            const float w2 = fW3[(u4 * 4 + 2) * 96 + w];
            const float w3 = fW3[(u4 * 4 + 3) * 96 + w];
            #pragma unroll
            for (int e = 0; e < EPB; e++) {
                float4 x = reinterpret_cast<const float4*>(sH2[e])[u4];
                acc[e] += x.x * w0 + x.y * w1 + x.z * w2 + x.w * w3;
            }
        }
        const float b = fb3[w];
        #pragma unroll
        for (int e = 0; e < EPB; e++) sWFC[e][w] = acc[e] + b;
    }
    __syncthreads();

    // ---- phase D: zs (t<64) | zg (64..95) | t1 (96..127) ----
    if (t < 64) {
        const int w = t;
        float accA[EPB], accB[EPB];
        #pragma unroll
        for (int e = 0; e < EPB; e++) { accA[e] = 0.f; accB[e] = 0.f; }
        // es @ Wss0[128:192]
        #pragma unroll 2
        for (int u4 = 0; u4 < 16; u4++) {
            const float w0 = Wss0[(128 + u4 * 4 + 0) * 64 + w];
            const float w1 = Wss0[(128 + u4 * 4 + 1) * 64 + w];
            const float w2 = Wss0[(128 + u4 * 4 + 2) * 64 + w];
            const float w3 = Wss0[(128 + u4 * 4 + 3) * 64 + w];
            #pragma unroll
            for (int e = 0; e < EPB; e++) {
                float4 x = reinterpret_cast<const float4*>(sES[e])[u4];
                accA[e] += x.x * w0 + x.y * w1 + x.z * w2 + x.w * w3;
            }
        }
        // ddev @ Wvv0[64:96]
        #pragma unroll 2
        for (int u4 = 0; u4 < 8; u4++) {
            const float w0 = Wvv0[(64 + u4 * 4 + 0) * 64 + w];
            const float w1 = Wvv0[(64 + u4 * 4 + 1) * 64 + w];
            const float w2 = Wvv0[(64 + u4 * 4 + 2) * 64 + w];
            const float w3 = Wvv0[(64 + u4 * 4 + 3) * 64 + w];
            #pragma unroll
            for (int e = 0; e < EPB; e++) {
                float4 x = reinterpret_cast<const float4*>(sDD[e])[u4];
                accB[e] += x.x * w0 + x.y * w1 + x.z * w2 + x.w * w3;
            }
        }
        #pragma unroll
        for (int e = 0; e < EPB; e++) {
            if (sOK[e]) {
                float4 pI = g_zsI[sI[e] * 64 + w];
                float4 pJ = g_zsJ[sJ[e] * 64 + w];
                float S = accA[e] + pI.w + pJ.w;
                float D = accB[e] + sSH[e][1] * (pI.x + pJ.x)
                                  + sSH[e][2] * (pI.y + pJ.y)
                                  + sSH[e][3] * (pI.z + pJ.z);
                float z = (sSH[e][0] * S + D) * INV_FAN;
                atomicAdd(&g_ns[sI[e] * MS + w], silu_f(z) * sWFC[e][w]);
            }
        }
    } else if (t < 96) {
        const int w = t - 64;
        float accA[EPB], accB[EPB];
        #pragma unroll
        for (int e = 0; e < EPB; e++) { accA[e] = 0.f; accB[e] = 0.f; }
        // es @ Wssg[128:192]
        #pragma unroll 2
        for (int u4 = 0; u4 < 16; u4++) {
            const float w0 = Wssg[(128 + u4 * 4 + 0) * 32 + w];
            const float w1 = Wssg[(128 + u4 * 4 + 1) * 32 + w];
            const float w2 = Wssg[(128 + u4 * 4 + 2) * 32 + w];
            const float w3 = Wssg[(128 + u4 * 4 + 3) * 32 + w];
            #pragma unroll
            for (int e = 0; e < EPB; e++) {
                float4 x = reinterpret_cast<const float4*>(sES[e])[u4];
                accA[e] += x.x * w0 + x.y * w1 + x.z * w2 + x.w * w3;
            }
        }
        // ddev @ Wvvg[64:96]
        #pragma unroll 2
        for (int u4 = 0; u4 < 8; u4++) {
            const float w0 = Wvvg[(64 + u4 * 4 + 0) * 32 + w];
            const float w1 = Wvvg[(64 + u4 * 4 + 1) * 32 + w];
            const float w2 = Wvvg[(64 + u4 * 4 + 2) * 32 + w];
            const float w3 = Wvvg[(64 + u4 * 4 + 3) * 32 + w];
            #pragma unroll
            for (int e = 0; e < EPB; e++) {
                float4 x = reinterpret_cast<const float4*>(sDD[e])[u4];
                accB[e] += x.x * w0 + x.y * w1 + x.z * w2 + x.w * w3;
            }
        }
        #pragma unroll
        for (int e = 0; e < EPB; e++) {
            float4 pI = g_zgI[sI[e] * 32 + w];
            float4 pJ = g_zgJ[sJ[e] * 32 + w];
            float S = accA[e] + pI.w + pJ.w;
            float D = accB[e] + sSH[e][1] * (pI.x + pJ.x)
                              + sSH[e][2] * (pI.y + pJ.y)
                              + sSH[e][3] * (pI.z + pJ.z);
            sSG[e][w] = sigm_f((sSH[e][0] * S + D) * INV_FAN);
        }
    } else {
        const int w = t - 96;
        float accA[EPB];
        #pragma unroll
        for (int e = 0; e < EPB; e++) accA[e] = 0.f;
        // es @ Wsv1[128:192]
        #pragma unroll 2
        for (int u4 = 0; u4 < 16; u4++) {
            const float w0 = Wsv1[(128 + u4 * 4 + 0) * 32 + w];
            const float w1 = Wsv1[(128 + u4 * 4 + 1) * 32 + w];
            const float w2 = Wsv1[(128 + u4 * 4 + 2) * 32 + w];
            const float w3 = Wsv1[(128 + u4 * 4 + 3) * 32 + w];
            #pragma unroll
            for (int e = 0; e < EPB; e++) {
                float4 x = reinterpret_cast<const float4*>(sES[e])[u4];
                accA[e] += x.x * w0 + x.y * w1 + x.z * w2 + x.w * w3;
            }
        }
        #pragma unroll
        for (int e = 0; e < EPB; e++) sT1[e][w] = accA[e];
    }
    __syncthreads();

    // ---- phase E: zv ----
    if (t < 96) {
        const int w = t & 31, ii = t >> 5;    // ii uniform per warp
        float acc[EPB];
        #pragma unroll
        for (int e = 0; e < EPB; e++) acc[e] = 0.f;
        // ev[:,ii] @ Wvs1[64:96]
        #pragma unroll 2
        for (int u4 = 0; u4 < 8; u4++) {
            const float w0 = Wvs1[(64 + u4 * 4 + 0) * 32 + w];
            const float w1 = Wvs1[(64 + u4 * 4 + 1) * 32 + w];
            const float w2 = Wvs1[(64 + u4 * 4 + 2) * 32 + w];
            const float w3 = Wvs1[(64 + u4 * 4 + 3) * 32 + w];
            #pragma unroll
            for (int e = 0; e < EPB; e++) {
                float4 x = reinterpret_cast<const float4*>(&sEV[e][ii][0])[u4];
                acc[e] += x.x * w0 + x.y * w1 + x.z * w2 + x.w * w3;
            }
        }
        #pragma unroll
        for (int e = 0; e < EPB; e++) {
            if (sOK[e]) {
                float4 qI = g_svI[sI[e] * 32 + w];
                float4 qJ = g_svJ[sJ[e] * 32 + w];
                float t2 = acc[e] + ((ii == 0) ? (qI.x + qJ.x)
                                  : (ii == 1) ? (qI.y + qJ.y)
                                              : (qI.z + qJ.z));
                float t1f = sT1[e][w] + qI.w + qJ.w;
                float zv = (t1f * sSH[e][1 + ii] + t2 * sSH[e][0]) * INV_FAN
                           * sSG[e][w] * sWFC[e][64 + w];
                atomicAdd(&g_nv[sI[e] * 96 + w * 3 + ii], zv);
            }
        }
    }
}

// ---------------- node post ----------------
__global__ __launch_bounds__(96) void k_node_post(
    const float* __restrict__ ppWs, const float* __restrict__ ppbs,
    const float* __restrict__ ppWv, const int* __restrict__ batch)
{
    const int n = blockIdx.x;
    const int t = threadIdx.x;
    __shared__ float sns[MS];
    __shared__ float snv[MV * 3];
    __shared__ float red[3];

    if (t < MS) sns[t] = g_ns[n * MS + t];
    snv[t] = g_nv[n * 96 + t];
    if (t < 3) red[t] = 0.f;
    __syncthreads();

    float ps = 0.f, ps2 = 0.f, pv2 = 0.f;
    if (t < MS) {
        float a = 0.f;
        #pragma unroll 8
        for (int u = 0; u < MS; u++) a += sns[u] * ppWs[u * MS + t];
        float val = a * INV8 + ppbs[t] + g_scs[n * MS + t];
        g_ps[n * MS + t] = val;
        ps = val; ps2 = val * val;
    }
    {
        const int w = t / 3, i = t - w * 3;
        float a = 0.f;
        #pragma unroll 8
        for (int u = 0; u < MV; u++) a += snv[u * 3 + i] * ppWv[u * MV + w];
        float val = a * INV_SQRT32 + g_scv[n * 96 + t];
        g_pv[n * 96 + t] = val;
        pv2 = val * val;
    }
    atomicAdd(&red[0], ps);
    atomicAdd(&red[1], ps2);
    atomicAdd(&red[2], pv2);
    __syncthreads();
    if (t == 0) {
        const int g = batch[n];
        atomicAdd(&g_stats[g * 4 + 0], red[0] * (1.f / 64.f));
        atomicAdd(&g_stats[g * 4 + 1], red[1] * (1.f / 64.f));
        atomicAdd(&g_stats[g * 4 + 2], red[2] * (1.f / 96.f));
        atomicAdd(&g_stats[g * 4 + 3], 1.f);
    }
}

// ---------------- group stats finalize ----------------
__global__ void k_stats() {
    const int g = threadIdx.x;
    if (g < NGROUP) {
        float cnt = fmaxf(g_stats[g * 4 + 3], 1.f);
        float mu  = g_stats[g * 4 + 0] / cnt;
        float vs  = fmaxf(g_stats[g * 4 + 1] / cnt - mu * mu, 0.f);
        float vv  = g_stats[g * 4 + 2] / cnt;
        g_norm[g * 3 + 0] = mu;
        g_norm[g * 3 + 1] = rsqrtf(vs + LN_EPS);
        g_norm[g * 3 + 2] = rsqrtf(vv + LN_EPS);
    }
}

// ---------------- finalize output ----------------
__global__ void k_finalize(
    const float* __restrict__ nf, const int* __restrict__ batch,
    const float* __restrict__ lnws, const float* __restrict__ lnbs,
    const float* __restrict__ lnwv, float* __restrict__ out, int N)
{
    const int total = N * DN;
    for (int idx = blockIdx.x * blockDim.x + threadIdx.x; idx < total;
         idx += gridDim.x * blockDim.x) {
        const int n = idx / DN;
        const int c = idx - n * DN;
        const int g = batch[n];
        float o;
        if (c < MS) {
            float mu = g_norm[g * 3 + 0], is = g_norm[g * 3 + 1];
            o = nf[idx] + (g_ps[n * MS + c] - mu) * is * lnws[c] + lnbs[c];
        } else {
            const int u3 = c - MS;
            float iv = g_norm[g * 3 + 2];
            o = nf[idx] + g_pv[n * 96 + u3] * iv * lnwv[u3 / 3];
        }
        out[idx] = o;
    }
}

// ---------------- launch ----------------
extern "C" void kernel_launch(void* const* d_in, const int* in_sizes, int n_in,
                              void* d_out, int out_size)
{
    const float* node_fea = (const float*)d_in[0];
    const float* onehot   = (const float*)d_in[1];
    const float* edge_sh  = (const float*)d_in[2];
    const float* edge_fea = (const float*)d_in[3];
    const float* ele      = (const float*)d_in[4];
    const int*   edge_idx = (const int*)  d_in[5];
    const int*   batch    = (const int*)  d_in[6];
    const float* lpWs = (const float*)d_in[7];
    const float* lpbs = (const float*)d_in[8];
    const float* lpWv = (const float*)d_in[9];
    const float* ppWs = (const float*)d_in[10];
    const float* ppbs = (const float*)d_in[11];
    const float* ppWv = (const float*)d_in[12];
    const float* scWs = (const float*)d_in[13];
    const float* scWv = (const float*)d_in[14];
    const float* Wss0 = (const float*)d_in[15];
    const float* Wvv0 = (const float*)d_in[16];
    const float* Wssg = (const float*)d_in[17];
    const float* Wvvg = (const float*)d_in[18];
    const float* Wsv1 = (const float*)d_in[19];
    const float* Wvs1 = (const float*)d_in[20];
    const float* fW1  = (const float*)d_in[21];
    const float* fb1  = (const float*)d_in[22];
    const float* fW2  = (const float*)d_in[23];
    const float* fb2  = (const float*)d_in[24];
    const float* fW3  = (const float*)d_in[25];
    const float* fb3  = (const float*)d_in[26];
    const float* lnws = (const float*)d_in[27];
    const float* lnbs = (const float*)d_in[28];
    const float* lnwv = (const float*)d_in[29];
    float* out = (float*)d_out;

    const int N = in_sizes[0] / DN;
    const int E = in_sizes[2] / 4;

    const int zt = N * DN + NGROUP * 4;
    k_zero<<<(zt + 255) / 256, 256>>>(N);
    k_node_pre<<<N, 128>>>(node_fea, onehot, lpWs, lpbs, lpWv, scWs, scWv,
                           Wss0, Wvv0, Wssg, Wvvg, Wsv1, Wvs1);
    k_edge<<<(E + EPB - 1) / EPB, 128>>>(edge_sh, edge_fea, ele, edge_idx,
                                         Wss0, Wvv0, Wssg, Wvvg, Wsv1, Wvs1,
                                         fW1, fb1, fW2, fb2, fW3, fb3, E);
    k_node_post<<<N, 96>>>(ppWs, ppbs, ppWv, batch);
    k_stats<<<1, 32>>>();
    k_finalize<<<(N * DN + 255) / 256, 256>>>(node_fea, batch, lnws, lnbs, lnwv, out, N);
}

// round 4
// speedup vs baseline: 4.7761x; 1.0896x over previous
#include <cuda_runtime.h>
#include <math.h>

// ---------------- problem constants ----------------
#define DN     160
#define MS     64
#define MV     32
#define NGROUP 16
#define FCIN   128
#define MAXN   10000
#define MAXE   320000
#define EPB    8

#define INV8        0.125f
#define INV16       0.0625f
#define INV_SQRT32  0.17677669529663687f
#define INV_SQRT128 0.08838834764831845f
#define INV_SQRT3   0.5773502691896258f
#define INV_FAN     0.05892556509887896f
#define LN_EPS      1e-5f

// ---------------- device scratch ----------------
__device__ float g_scs[MAXN * MS];
__device__ float g_scv[MAXN * MV * 3];
__device__ float g_ns [MAXN * MS];
__device__ float g_nv [MAXN * MV * 3];
__device__ float g_ps [MAXN * MS];
__device__ float g_pv [MAXN * MV * 3];
__device__ float g_stats[NGROUP * 4];
__device__ float g_norm [NGROUP * 3];

// per-node precomputed partials {P_c0,P_c1,P_c2, A}
__device__ float4 g_zsI[MAXN * 64];
__device__ float4 g_zsJ[MAXN * 64];
__device__ float4 g_zgI[MAXN * 32];
__device__ float4 g_zgJ[MAXN * 32];
__device__ float4 g_svI[MAXN * 32];
__device__ float4 g_svJ[MAXN * 32];

// per-edge GEMM intermediates
__device__ float g_H1 [(size_t)MAXE * 64];
__device__ float g_H2 [(size_t)MAXE * 64];
__device__ float g_WFC[(size_t)MAXE * 96];
__device__ float g_Ces[(size_t)MAXE * 128];
__device__ float g_Cdd[(size_t)MAXE * 96];
__device__ float g_dd [(size_t)MAXE * 32];
// concatenated weights
__device__ float g_Wes[64 * 128];
__device__ float g_Wdd[32 * 96];

__device__ __forceinline__ float silu_f(float x) { return x / (1.f + __expf(-x)); }
__device__ __forceinline__ float sigm_f(float x) { return 1.f / (1.f + __expf(-x)); }

__device__ __forceinline__ unsigned int f2tf32(float x) {
    unsigned int r;
    asm("cvt.rna.tf32.f32 %0, %1;" : "=r"(r) : "f"(x));
    return r;
}
__device__ __forceinline__ void mma8(float* c, unsigned int a0, unsigned int a1,
                                     unsigned int a2, unsigned int a3,
                                     unsigned int b0, unsigned int b1) {
    asm volatile(
        "mma.sync.aligned.m16n8k8.row.col.f32.tf32.tf32.f32 "
        "{%0,%1,%2,%3}, {%4,%5,%6,%7}, {%8,%9}, {%0,%1,%2,%3};"
        : "+f"(c[0]), "+f"(c[1]), "+f"(c[2]), "+f"(c[3])
        : "r"(a0), "r"(a1), "r"(a2), "r"(a3), "r"(b0), "r"(b1));
}

// ---------------- zero scratch ----------------
__global__ void k_zero(int N) {
    int tot = N * DN + NGROUP * 4;
    for (int i = blockIdx.x * blockDim.x + threadIdx.x; i < tot; i += gridDim.x * blockDim.x) {
        if (i < N * MS)      g_ns[i] = 0.f;
        else if (i < N * DN) g_nv[i - N * MS] = 0.f;
        else                 g_stats[i - N * DN] = 0.f;
    }
}

// ---------------- concat-weight prep ----------------
__global__ void k_prepW(const float* __restrict__ Wss0, const float* __restrict__ Wssg,
                        const float* __restrict__ Wsv1, const float* __restrict__ Wvv0,
                        const float* __restrict__ Wvvg) {
    int t = blockIdx.x * blockDim.x + threadIdx.x;
    if (t < 64 * 128) {
        int u = t >> 7, n = t & 127;
        float v;
        if (n < 64)      v = Wss0[(128 + u) * 64 + n];
        else if (n < 96) v = Wssg[(128 + u) * 32 + (n - 64)];
        else             v = Wsv1[(128 + u) * 32 + (n - 96)];
        g_Wes[t] = v;
    } else if (t < 64 * 128 + 32 * 96) {
        int i = t - 64 * 128;
        int u = i / 96, n = i - u * 96;
        g_Wdd[i] = (n < 64) ? Wvv0[(64 + u) * 64 + n] : Wvvg[(64 + u) * 32 + (n - 64)];
    }
}

// ---------------- dd prep: dd_ev[e][u] = <ev[e,u,:], sh1>/sqrt3 ----------------
__global__ void k_dd(const float* __restrict__ edge_fea, const float* __restrict__ edge_sh, int E) {
    int idx = blockIdx.x * blockDim.x + threadIdx.x;
    if (idx >= E * 32) return;
    int e = idx >> 5, u = idx & 31;
    float s1 = edge_sh[e * 4 + 1], s2 = edge_sh[e * 4 + 2], s3 = edge_sh[e * 4 + 3];
    const float* ev = edge_fea + (size_t)e * DN + 64 + u * 3;
    g_dd[idx] = (ev[0] * s1 + ev[1] * s2 + ev[2] * s3) * INV_SQRT3;
}

// ---------------- generic 3xTF32 mma GEMM: C[E,N] = act(A[E,K]@W[K,N] + b) ----------------
template<int K, int N, int ACT, int HASB>
__global__ void __launch_bounds__(128) k_mma(
    const float* __restrict__ A, long lda,
    const float* __restrict__ W, const float* __restrict__ bias,
    float* __restrict__ C, int E)
{
    constexpr int KP = K + 4;
    constexpr int NB = N / 8;
    extern __shared__ unsigned int smw[];
    unsigned int* sHi = smw;             // [N][KP] tf32 bits
    unsigned int* sLo = smw + N * KP;

    const int t = threadIdx.x;
    const int lane = t & 31, warp = t >> 5;

    for (int idx = t; idx < K * N; idx += 128) {
        int k = idx / N, n = idx - k * N;
        float w = W[idx];
        unsigned int hi = f2tf32(w);
        sHi[n * KP + k] = hi;
        sLo[n * KP + k] = f2tf32(w - __uint_as_float(hi));
    }
    __syncthreads();

    const int r0 = blockIdx.x * 64 + warp * 16 + (lane >> 2);
    const int r1 = r0 + 8;
    const long ar0 = (long)min(r0, E - 1) * lda;
    const long ar1 = (long)min(r1, E - 1) * lda;

    float acc[NB][4];
    #pragma unroll
    for (int nb = 0; nb < NB; nb++) {
        acc[nb][0] = 0.f; acc[nb][1] = 0.f; acc[nb][2] = 0.f; acc[nb][3] = 0.f;
    }

    #pragma unroll
    for (int kb = 0; kb < K / 8; kb++) {
        const int c = kb * 8 + (lane & 3);
        float a0 = __ldg(&A[ar0 + c]);
        float a1 = __ldg(&A[ar1 + c]);
        float a2 = __ldg(&A[ar0 + c + 4]);
        float a3 = __ldg(&A[ar1 + c + 4]);
        unsigned int h0 = f2tf32(a0), h1 = f2tf32(a1), h2 = f2tf32(a2), h3 = f2tf32(a3);
        unsigned int l0 = f2tf32(a0 - __uint_as_float(h0));
        unsigned int l1 = f2tf32(a1 - __uint_as_float(h1));
        unsigned int l2 = f2tf32(a2 - __uint_as_float(h2));
        unsigned int l3 = f2tf32(a3 - __uint_as_float(h3));
        const int koff = kb * 8 + (lane & 3);
        const int nbase = lane >> 2;
        #pragma unroll
        for (int nb = 0; nb < NB; nb++) {
            int off = (nb * 8 + nbase) * KP + koff;
            unsigned int bh0 = sHi[off], bh1 = sHi[off + 4];
            unsigned int bl0 = sLo[off], bl1 = sLo[off + 4];
            mma8(acc[nb], h0, h1, h2, h3, bh0, bh1);
            mma8(acc[nb], l0, l1, l2, l3, bh0, bh1);
            mma8(acc[nb], h0, h1, h2, h3, bl0, bl1);
        }
    }

    #pragma unroll
    for (int nb = 0; nb < NB; nb++) {
        int n = nb * 8 + 2 * (lane & 3);
        float b0 = 0.f, b1 = 0.f;
        if (HASB) { b0 = __ldg(&bias[n]); b1 = __ldg(&bias[n + 1]); }
        float v0 = acc[nb][0] + b0, v1 = acc[nb][1] + b1;
        float v2 = acc[nb][2] + b0, v3 = acc[nb][3] + b1;
        if (ACT) { v0 = silu_f(v0); v1 = silu_f(v1); v2 = silu_f(v2); v3 = silu_f(v3); }
        if (r0 < E) *reinterpret_cast<float2*>(&C[(long)r0 * N + n]) = make_float2(v0, v1);
        if (r1 < E) *reinterpret_cast<float2*>(&C[(long)r1 * N + n]) = make_float2(v2, v3);
    }
}

// ---------------- node pre: lp + self-connection + edge-partial precompute ----------------
__global__ __launch_bounds__(128) void k_node_pre(
    const float* __restrict__ nf, const float* __restrict__ onehot,
    const float* __restrict__ lpWs, const float* __restrict__ lpbs,
    const float* __restrict__ lpWv,
    const float* __restrict__ scWs, const float* __restrict__ scWv,
    const float* __restrict__ Wss0, const float* __restrict__ Wvv0,
    const float* __restrict__ Wssg, const float* __restrict__ Wvvg,
    const float* __restrict__ Wsv1, const float* __restrict__ Wvs1)
{
    const int n = blockIdx.x;
    const int t = threadIdx.x;
    __shared__ float sIn[MS];
    __shared__ float vIn[MV * 3];
    __shared__ float sO [MS];
    __shared__ float vO [MV * 3];
    __shared__ int ssp;

    if (t < MS) sIn[t] = nf[n * DN + t];
    if (t < 96) vIn[t] = nf[n * DN + MS + t];
    if (t == 0) {
        int sp = 0; float best = onehot[n * 4];
        #pragma unroll
        for (int k = 1; k < 4; k++) { float v = onehot[n * 4 + k]; if (v > best) { best = v; sp = k; } }
        ssp = sp;
    }
    __syncthreads();
    const int sp = ssp;

    if (t < MS) {
        float a = 0.f, b = 0.f;
        #pragma unroll 8
        for (int u = 0; u < MS; u++) {
            float x = sIn[u];
            a += x * lpWs[u * MS + t];
            b += x * scWs[(u * 4 + sp) * MS + t];
        }
        sO[t] = a * INV8 + lpbs[t];
        g_scs[n * MS + t] = b * INV16;
    }
    if (t < 96) {
        const int w = t / 3, i = t - w * 3;
        float a = 0.f, b = 0.f;
        #pragma unroll 8
        for (int u = 0; u < MV; u++) {
            float x = vIn[u * 3 + i];
            a += x * lpWv[u * MV + w];
            b += x * scWv[(u * 4 + sp) * MV + w];
        }
        vO[w * 3 + i] = a * INV_SQRT32;
        g_scv[n * 96 + w * 3 + i] = b * INV_SQRT128;
    }
    __syncthreads();

    if (t < 64) {
        const int w = t;
        float p0 = 0.f, p1 = 0.f, p2 = 0.f, q0 = 0.f, q1 = 0.f, q2 = 0.f;
        #pragma unroll 4
        for (int u = 0; u < 32; u++) {
            float wa = Wvv0[u * 64 + w];
            float wb = Wvv0[(32 + u) * 64 + w];
            float x0 = vO[u * 3], x1 = vO[u * 3 + 1], x2 = vO[u * 3 + 2];
            p0 += x0 * wa; p1 += x1 * wa; p2 += x2 * wa;
            q0 += x0 * wb; q1 += x1 * wb; q2 += x2 * wb;
        }
        float a = 0.f, b = 0.f;
        #pragma unroll 8
        for (int u = 0; u < 64; u++) {
            float x = sO[u];
            a += x * Wss0[u * 64 + w];
            b += x * Wss0[(64 + u) * 64 + w];
        }
        g_zsI[n * 64 + w] = make_float4(p0 * INV_SQRT3, p1 * INV_SQRT3, p2 * INV_SQRT3, a);
        g_zsJ[n * 64 + w] = make_float4(q0 * INV_SQRT3, q1 * INV_SQRT3, q2 * INV_SQRT3, b);
    } else if (t < 96) {
        const int w = t - 64;
        float p0 = 0.f, p1 = 0.f, p2 = 0.f, q0 = 0.f, q1 = 0.f, q2 = 0.f;
        #pragma unroll 4
        for (int u = 0; u < 32; u++) {
            float wa = Wvvg[u * 32 + w];
            float wb = Wvvg[(32 + u) * 32 + w];
            float x0 = vO[u * 3], x1 = vO[u * 3 + 1], x2 = vO[u * 3 + 2];
            p0 += x0 * wa; p1 += x1 * wa; p2 += x2 * wa;
            q0 += x0 * wb; q1 += x1 * wb; q2 += x2 * wb;
        }
        float a = 0.f, b = 0.f;
        #pragma unroll 8
        for (int u = 0; u < 64; u++) {
            float x = sO[u];
            a += x * Wssg[u * 32 + w];
            b += x * Wssg[(64 + u) * 32 + w];
        }
        g_zgI[n * 32 + w] = make_float4(p0 * INV_SQRT3, p1 * INV_SQRT3, p2 * INV_SQRT3, a);
        g_zgJ[n * 32 + w] = make_float4(q0 * INV_SQRT3, q1 * INV_SQRT3, q2 * INV_SQRT3, b);
    } else {
        const int w = t - 96;
        float p0 = 0.f, p1 = 0.f, p2 = 0.f, q0 = 0.f, q1 = 0.f, q2 = 0.f;
        #pragma unroll 4
        for (int u = 0; u < 32; u++) {
            float wa = Wvs1[u * 32 + w];
            float wb = Wvs1[(32 + u) * 32 + w];
            float x0 = vO[u * 3], x1 = vO[u * 3 + 1], x2 = vO[u * 3 + 2];
            p0 += x0 * wa; p1 += x1 * wa; p2 += x2 * wa;
            q0 += x0 * wb; q1 += x1 * wb; q2 += x2 * wb;
        }
        float a = 0.f, b = 0.f;
        #pragma unroll 8
        for (int u = 0; u < 64; u++) {
            float x = sO[u];
            a += x * Wsv1[u * 32 + w];
            b += x * Wsv1[(64 + u) * 32 + w];
        }
        g_svI[n * 32 + w] = make_float4(p0, p1, p2, a);
        g_svJ[n * 32 + w] = make_float4(q0, q1, q2, b);
    }
}

// ---------------- combine kernel: gather + sh-combine + scatter ----------------
__global__ __launch_bounds__(128) void k_combine(
    const float* __restrict__ edge_sh, const float* __restrict__ edge_fea,
    const int* __restrict__ edge_index, const float* __restrict__ Wvs1, int E)
{
    __shared__ float sEV[EPB][3][32];
    __shared__ float sWv[32][33];
    __shared__ float sSG[EPB][32];
    __shared__ float sT1[EPB][32];
    __shared__ float sQ [EPB][3][32];
    __shared__ float sSH[EPB][4];
    __shared__ int   sI[EPB], sJ[EPB], sOK[EPB];

    const int t  = threadIdx.x;
    const int e0 = blockIdx.x * EPB;

    if (t < EPB) {
        int eg = e0 + t;
        int ok = (eg < E);
        sOK[t] = ok;
        sI[t]  = ok ? edge_index[eg]     : 0;
        sJ[t]  = ok ? edge_index[E + eg] : 0;
    }
    if (t >= 32 && t < 32 + EPB * 4) {
        int q = t - 32;
        int e = q >> 2, k = q & 3;
        int eg = e0 + e;
        sSH[e][k] = (eg < E) ? edge_sh[eg * 4 + k] : 0.f;
    }
    for (int idx = t; idx < 32 * 32; idx += 128) {
        int u = idx >> 5, w = idx & 31;
        sWv[u][w] = Wvs1[(64 + u) * 32 + w];
    }
    __syncthreads();

    for (int id = t; id < EPB * 96; id += 128) {
        int e = id / 96, c = id - e * 96;
        int u = c / 3, ii = c - u * 3;
        sEV[e][ii][u] = sOK[e] ? edge_fea[(size_t)(e0 + e) * DN + 64 + c] : 0.f;
    }
    __syncthreads();

    if (t < 64) {
        const int w = t;
        #pragma unroll
        for (int e = 0; e < EPB; e++) {
            if (sOK[e]) {
                const int i = sI[e], j = sJ[e];
                float4 pI = __ldg(&g_zsI[i * 64 + w]);
                float4 pJ = __ldg(&g_zsJ[j * 64 + w]);
                float S = __ldg(&g_Ces[(size_t)(e0 + e) * 128 + w]) + pI.w + pJ.w;
                float D = __ldg(&g_Cdd[(size_t)(e0 + e) * 96 + w])
                          + sSH[e][1] * (pI.x + pJ.x)
                          + sSH[e][2] * (pI.y + pJ.y)
                          + sSH[e][3] * (pI.z + pJ.z);
                float z = (sSH[e][0] * S + D) * INV_FAN;
                float val = silu_f(z) * __ldg(&g_WFC[(size_t)(e0 + e) * 96 + w]);
                atomicAdd(&g_ns[i * MS + w], val);
            }
        }
    } else if (t < 96) {
        const int w = t - 64;
        #pragma unroll
        for (int e = 0; e < EPB; e++) {
            const int i = sI[e], j = sJ[e];
            float4 pI = __ldg(&g_zgI[i * 32 + w]);
            float4 pJ = __ldg(&g_zgJ[j * 32 + w]);
            float S = __ldg(&g_Ces[(size_t)(e0 + e) * 128 + 64 + w]) + pI.w + pJ.w;
            float D = __ldg(&g_Cdd[(size_t)(e0 + e) * 96 + 64 + w])
                      + sSH[e][1] * (pI.x + pJ.x)
                      + sSH[e][2] * (pI.y + pJ.y)
                      + sSH[e][3] * (pI.z + pJ.z);
            sSG[e][w] = sigm_f((sSH[e][0] * S + D) * INV_FAN);
        }
    } else {
        const int w = t - 96;
        #pragma unroll
        for (int e = 0; e < EPB; e++) {
            const int i = sI[e], j = sJ[e];
            float4 qI = __ldg(&g_svI[i * 32 + w]);
            float4 qJ = __ldg(&g_svJ[j * 32 + w]);
            sT1[e][w] = __ldg(&g_Ces[(size_t)(e0 + e) * 128 + 96 + w]) + qI.w + qJ.w;
            sQ[e][0][w] = qI.x + qJ.x;
            sQ[e][1][w] = qI.y + qJ.y;
            sQ[e][2][w] = qI.z + qJ.z;
        }
    }
    __syncthreads();

    if (t < 96) {
        const int w = t & 31, ii = t >> 5;
        #pragma unroll
        for (int e = 0; e < EPB; e++) {
            if (sOK[e]) {
                float acc = sQ[e][ii][w];
                #pragma unroll 8
                for (int u = 0; u < 32; u++) acc += sEV[e][ii][u] * sWv[u][w];
                float zv = (sT1[e][w] * sSH[e][1 + ii] + acc * sSH[e][0]) * INV_FAN
                           * sSG[e][w] * __ldg(&g_WFC[(size_t)(e0 + e) * 96 + 64 + w]);
                atomicAdd(&g_nv[sI[e] * 96 + w * 3 + ii], zv);
            }
        }
    }
}

// ---------------- node post ----------------
__global__ __launch_bounds__(96) void k_node_post(
    const float* __restrict__ ppWs, const float* __restrict__ ppbs,
    const float* __restrict__ ppWv, const int* __restrict__ batch)
{
    const int n = blockIdx.x;
    const int t = threadIdx.x;
    __shared__ float sns[MS];
    __shared__ float snv[MV * 3];
    __shared__ float red[3];

    if (t < MS) sns[t] = g_ns[n * MS + t];
    snv[t] = g_nv[n * 96 + t];
    if (t < 3) red[t] = 0.f;
    __syncthreads();

    float ps = 0.f, ps2 = 0.f, pv2 = 0.f;
    if (t < MS) {
        float a = 0.f;
        #pragma unroll 8
        for (int u = 0; u < MS; u++) a += sns[u] * ppWs[u * MS + t];
        float val = a * INV8 + ppbs[t] + g_scs[n * MS + t];
        g_ps[n * MS + t] = val;
        ps = val; ps2 = val * val;
    }
    {
        const int w = t / 3, i = t - w * 3;
        float a = 0.f;
        #pragma unroll 8
        for (int u = 0; u < MV; u++) a += snv[u * 3 + i] * ppWv[u * MV + w];
        float val = a * INV_SQRT32 + g_scv[n * 96 + t];
        g_pv[n * 96 + t] = val;
        pv2 = val * val;
    }
    atomicAdd(&red[0], ps);
    atomicAdd(&red[1], ps2);
    atomicAdd(&red[2], pv2);
    __syncthreads();
    if (t == 0) {
        const int g = batch[n];
        atomicAdd(&g_stats[g * 4 + 0], red[0] * (1.f / 64.f));
        atomicAdd(&g_stats[g * 4 + 1], red[1] * (1.f / 64.f));
        atomicAdd(&g_stats[g * 4 + 2], red[2] * (1.f / 96.f));
        atomicAdd(&g_stats[g * 4 + 3], 1.f);
    }
}

// ---------------- group stats finalize ----------------
__global__ void k_stats() {
    const int g = threadIdx.x;
    if (g < NGROUP) {
        float cnt = fmaxf(g_stats[g * 4 + 3], 1.f);
        float mu  = g_stats[g * 4 + 0] / cnt;
        float vs  = fmaxf(g_stats[g * 4 + 1] / cnt - mu * mu, 0.f);
        float vv  = g_stats[g * 4 + 2] / cnt;
        g_norm[g * 3 + 0] = mu;
        g_norm[g * 3 + 1] = rsqrtf(vs + LN_EPS);
        g_norm[g * 3 + 2] = rsqrtf(vv + LN_EPS);
    }
}

// ---------------- finalize output ----------------
__global__ void k_finalize(
    const float* __restrict__ nf, const int* __restrict__ batch,
    const float* __restrict__ lnws, const float* __restrict__ lnbs,
    const float* __restrict__ lnwv, float* __restrict__ out, int N)
{
    const int total = N * DN;
    for (int idx = blockIdx.x * blockDim.x + threadIdx.x; idx < total;
         idx += gridDim.x * blockDim.x) {
        const int n = idx / DN;
        const int c = idx - n * DN;
        const int g = batch[n];
        float o;
        if (c < MS) {
            float mu = g_norm[g * 3 + 0], is = g_norm[g * 3 + 1];
            o = nf[idx] + (g_ps[n * MS + c] - mu) * is * lnws[c] + lnbs[c];
        } else {
            const int u3 = c - MS;
            float iv = g_norm[g * 3 + 2];
            o = nf[idx] + g_pv[n * 96 + u3] * iv * lnwv[u3 / 3];
        }
        out[idx] = o;
    }
}

// ---------------- launch ----------------
extern "C" void kernel_launch(void* const* d_in, const int* in_sizes, int n_in,
                              void* d_out, int out_size)
{
    const float* node_fea = (const float*)d_in[0];
    const float* onehot   = (const float*)d_in[1];
    const float* edge_sh  = (const float*)d_in[2];
    const float* edge_fea = (const float*)d_in[3];
    const float* ele      = (const float*)d_in[4];
    const int*   edge_idx = (const int*)  d_in[5];
    const int*   batch    = (const int*)  d_in[6];
    const float* lpWs = (const float*)d_in[7];
    const float* lpbs = (const float*)d_in[8];
    const float* lpWv = (const float*)d_in[9];
    const float* ppWs = (const float*)d_in[10];
    const float* ppbs = (const float*)d_in[11];
    const float* ppWv = (const float*)d_in[12];
    const float* scWs = (const float*)d_in[13];
    const float* scWv = (const float*)d_in[14];
    const float* Wss0 = (const float*)d_in[15];
    const float* Wvv0 = (const float*)d_in[16];
    const float* Wssg = (const float*)d_in[17];
    const float* Wvvg = (const float*)d_in[18];
    const float* Wsv1 = (const float*)d_in[19];
    const float* Wvs1 = (const float*)d_in[20];
    const float* fW1  = (const float*)d_in[21];
    const float* fb1  = (const float*)d_in[22];
    const float* fW2  = (const float*)d_in[23];
    const float* fb2  = (const float*)d_in[24];
    const float* fW3  = (const float*)d_in[25];
    const float* fb3  = (const float*)d_in[26];
    const float* lnws = (const float*)d_in[27];
    const float* lnbs = (const float*)d_in[28];
    const float* lnwv = (const float*)d_in[29];
    float* out = (float*)d_out;

    const int N = in_sizes[0] / DN;
    const int E = in_sizes[2] / 4;

    // device-symbol addresses for GEMM I/O
    float *pH1, *pH2, *pWFC, *pCes, *pCdd, *pdd, *pWes, *pWdd;
    cudaGetSymbolAddress((void**)&pH1,  g_H1);
    cudaGetSymbolAddress((void**)&pH2,  g_H2);
    cudaGetSymbolAddress((void**)&pWFC, g_WFC);
    cudaGetSymbolAddress((void**)&pCes, g_Ces);
    cudaGetSymbolAddress((void**)&pCdd, g_Cdd);
    cudaGetSymbolAddress((void**)&pdd,  g_dd);
    cudaGetSymbolAddress((void**)&pWes, g_Wes);
    cudaGetSymbolAddress((void**)&pWdd, g_Wdd);

    auto smem_of = [](int Kk, int Nn) { return 2 * Nn * (Kk + 4) * (int)sizeof(float); };
    cudaFuncSetAttribute(k_mma<128, 64, 1, 1>, cudaFuncAttributeMaxDynamicSharedMemorySize, smem_of(128, 64));
    cudaFuncSetAttribute(k_mma< 64, 64, 1, 1>, cudaFuncAttributeMaxDynamicSharedMemorySize, smem_of(64, 64));
    cudaFuncSetAttribute(k_mma< 64, 96, 0, 1>, cudaFuncAttributeMaxDynamicSharedMemorySize, smem_of(64, 96));
    cudaFuncSetAttribute(k_mma< 64,128, 0, 0>, cudaFuncAttributeMaxDynamicSharedMemorySize, smem_of(64, 128));
    cudaFuncSetAttribute(k_mma< 32, 96, 0, 0>, cudaFuncAttributeMaxDynamicSharedMemorySize, smem_of(32, 96));

    const int gemm_grid = (E + 63) / 64;
    const int zt = N * DN + NGROUP * 4;

    k_zero<<<(zt + 255) / 256, 256>>>(N);
    k_prepW<<<(64 * 128 + 32 * 96 + 255) / 256, 256>>>(Wss0, Wssg, Wsv1, Wvv0, Wvvg);
    k_node_pre<<<N, 128>>>(node_fea, onehot, lpWs, lpbs, lpWv, scWs, scWv,
                           Wss0, Wvv0, Wssg, Wvvg, Wsv1, Wvs1);
    k_dd<<<(E * 32 + 255) / 256, 256>>>(edge_fea, edge_sh, E);

    k_mma<128, 64, 1, 1><<<gemm_grid, 128, smem_of(128, 64)>>>(ele, 128, fW1, fb1, pH1, E);
    k_mma< 64, 64, 1, 1><<<gemm_grid, 128, smem_of(64, 64)>>>(pH1, 64, fW2, fb2, pH2, E);
    k_mma< 64, 96, 0, 1><<<gemm_grid, 128, smem_of(64, 96)>>>(pH2, 64, fW3, fb3, pWFC, E);
    k_mma< 64,128, 0, 0><<<gemm_grid, 128, smem_of(64, 128)>>>(edge_fea, DN, pWes, nullptr, pCes, E);
    k_mma< 32, 96, 0, 0><<<gemm_grid, 128, smem_of(32, 96)>>>(pdd, 32, pWdd, nullptr, pCdd, E);

    k_combine<<<(E + EPB - 1) / EPB, 128>>>(edge_sh, edge_fea, edge_idx, Wvs1, E);
    k_node_post<<<N, 96>>>(ppWs, ppbs, ppWv, batch);
    k_stats<<<1, 32>>>();
    k_finalize<<<(N * DN + 255) / 256, 256>>>(node_fea, batch, lnws, lnbs, lnwv, out, N);
}